// round 11
// baseline (speedup 1.0000x reference)
#include <cuda_runtime.h>

// QuantumLayer, 2-kernel split + PDL overlap; eval slimmed to fit registers:
//  z_w(x) = sum_{u,v} C[w][u][v]*p01[u]*p23[v], features (1, cos x, sin x).
// Kernel 1 (1 block): shuffle-parallel C builder -> g_C.
// Kernel 2 (PDL secondary, EPT=1): prologue overlaps builder, then
// cudaGridDependencySynchronize() -> C -> packed f32x2 contraction.
// Live set ~58 regs < 73-reg cap (7 blocks/SM) -> no local spills.

#define TPB  128
#define NBLK 1036                   // 7 blocks/SM * 148 SMs, all resident
#define STRIDE (NBLK * TPB)

typedef unsigned long long ull;

__device__ float4 g_C[81];   // [u*9+v] -> (C_w0, C_w1, C_w2, C_w3)

__device__ __forceinline__ ull pk2(float lo, float hi) {
    ull r; asm("mov.b64 %0,{%1,%2};" : "=l"(r) : "f"(lo), "f"(hi)); return r;
}
__device__ __forceinline__ void upk2(ull a, float& lo, float& hi) {
    asm("mov.b64 {%0,%1},%2;" : "=f"(lo), "=f"(hi) : "l"(a));
}
__device__ __forceinline__ ull fma2(ull a, ull b, ull c) {
    ull d; asm("fma.rn.f32x2 %0,%1,%2,%3;" : "=l"(d) : "l"(a), "l"(b), "l"(c)); return d;
}
__device__ __forceinline__ ull mul2(ull a, ull b) {
    ull d; asm("mul.rn.f32x2 %0,%1,%2;" : "=l"(d) : "l"(a), "l"(b)); return d;
}

// ---------------------------------------------------------------------------
// Kernel 1: shuffle-parallel build of C. Thread tid = j*16 + i owns U[i][j].
// ---------------------------------------------------------------------------
__global__ void build_coeff_kernel(const float* __restrict__ weights) {
    cudaTriggerProgrammaticLaunchCompletion();   // let eval's prologue start now
    __shared__ float sUr[16][16], sUi[16][16];
    __shared__ float sM[256 * 4];                // [(j*16+k)*4 + w]
    const int tid = threadIdx.x;
    const int i = tid & 15;

    float vr = (i == (tid >> 4)) ? 1.0f : 0.0f;
    float vi = 0.0f;
#pragma unroll
    for (int l = 0; l < 5; ++l) {
#pragma unroll
        for (int w = 0; w < 4; ++w) {
            const float phi   = __ldg(&weights[(l * 4 + w) * 3 + 0]);
            const float theta = __ldg(&weights[(l * 4 + w) * 3 + 1]);
            const float omega = __ldg(&weights[(l * 4 + w) * 3 + 2]);
            float sp, cp, sm, cm, st, ct;
            __sincosf(0.5f * (phi + omega), &sp, &cp);
            __sincosf(0.5f * (phi - omega), &sm, &cm);
            __sincosf(0.5f * theta, &st, &ct);
            const int m = 8 >> w;
            const float pr = __shfl_xor_sync(0xffffffffu, vr, m);
            const float pi = __shfl_xor_sync(0xffffffffu, vi, m);
            const bool bit = (i & m) != 0;
            const float cAr = cp * ct;
            const float cAi = bit ? sp * ct : -sp * ct;
            const float cBr = bit ? cm * st : -cm * st;
            const float cBi = -sm * st;
            const float nvr = cAr * vr - cAi * vi + cBr * pr - cBi * pi;
            const float nvi = cAr * vi + cAi * vr + cBr * pi + cBi * pr;
            vr = nvr; vi = nvi;
        }
        const int r = (l % 3) + 1;
#pragma unroll
        for (int w = 0; w < 4; ++w) {
            const int mc = 8 >> w;
            const int mt = 8 >> ((w + r) & 3);
            const float pr = __shfl_xor_sync(0xffffffffu, vr, mt);
            const float pi = __shfl_xor_sync(0xffffffffu, vi, mt);
            if (i & mc) { vr = pr; vi = pi; }
        }
    }
    sUr[i][tid >> 4] = vr;
    sUi[i][tid >> 4] = vi;
    __syncthreads();

    {   // M_w[j][k] = sum_i sign_w(i) Re(conj U_ij * U_ik)
        const int j = tid >> 4, k = tid & 15;
        float m0 = 0.f, m1 = 0.f, m2 = 0.f, m3 = 0.f;
#pragma unroll
        for (int ii = 0; ii < 16; ++ii) {
            const float p = sUr[ii][j] * sUr[ii][k] + sUi[ii][j] * sUi[ii][k];
            m0 += (ii & 8) ? -p : p;
            m1 += (ii & 4) ? -p : p;
            m2 += (ii & 2) ? -p : p;
            m3 += (ii & 1) ? -p : p;
        }
        sM[tid * 4 + 0] = m0; sM[tid * 4 + 1] = m1;
        sM[tid * 4 + 2] = m2; sM[tid * 4 + 3] = m3;
    }
    __syncthreads();

    if (tid < 81) {  // project M_w onto (1, cos, sin)^{x4} basis
        const int t0 = tid / 27, t1 = (tid / 9) % 3, t2 = (tid / 3) % 3, t3 = tid % 3;
        const int tt[4] = {t0, t1, t2, t3};
        float a0 = 0.f, a1 = 0.f, a2 = 0.f, a3 = 0.f;
#pragma unroll
        for (int b = 0; b < 16; ++b) {
            int j = 0, k = 0; float sgn = 1.0f;
#pragma unroll
            for (int q = 0; q < 4; ++q) {
                const int o = (b >> q) & 1;
                const int ti = tt[q];
                int jq, kq;
                if (ti == 2) { jq = o; kq = 1 - o; }
                else { jq = o; kq = o; if (ti == 1 && o) sgn = -sgn; }
                j = (j << 1) | jq;
                k = (k << 1) | kq;
            }
            const float* m = &sM[(j * 16 + k) * 4];
            a0 += sgn * m[0]; a1 += sgn * m[1];
            a2 += sgn * m[2]; a3 += sgn * m[3];
        }
        const int u = t0 * 3 + t1, v = t2 * 3 + t3;
        g_C[u * 9 + v] = make_float4(a0 * 0.0625f, a1 * 0.0625f,
                                     a2 * 0.0625f, a3 * 0.0625f);
    }
}

// ---------------------------------------------------------------------------
// Kernel 2 (PDL secondary): EPT=1, grid-stride, slim register footprint.
// ---------------------------------------------------------------------------
__global__ __launch_bounds__(TPB, 7)
void qforward_kernel(const float4* __restrict__ x, float4* __restrict__ out, int B) {
    __shared__ __align__(16) ull shC[162];       // [uv][{w01, w23}]

    int idx = blockIdx.x * TPB + threadIdx.x;

    // ---------- prologue: first x load overlaps the builder ----------
    float4 xv = make_float4(0.f, 0.f, 0.f, 0.f);
    if (idx < B) xv = x[idx];

    // ---------- wait for builder's g_C, stage to shared ----------
    cudaGridDependencySynchronize();
    if (threadIdx.x < 81) {
        const float4 c = g_C[threadIdx.x];
        shC[2 * threadIdx.x]     = pk2(c.x, c.y);
        shC[2 * threadIdx.x + 1] = pk2(c.z, c.w);
    }
    __syncthreads();

    const ulonglong2* __restrict__ C2 = reinterpret_cast<const ulonglong2*>(shC);
    const ull ONE = pk2(1.0f, 1.0f);

    while (idx < B) {
        // features: p23 packed (feeds inner chains), p01 factors as scalars
        float c2, s2, c3, s3;
        __sincosf(xv.z, &s2, &c2);
        __sincosf(xv.w, &s3, &c3);
        ull p23[9];
        {
            const ull c2d = pk2(c2, c2), s2d = pk2(s2, s2);
            const ull c3d = pk2(c3, c3), s3d = pk2(s3, s3);
            p23[0] = ONE; p23[1] = c3d; p23[2] = s3d;
            p23[3] = c2d; p23[4] = mul2(c2d, c3d); p23[5] = mul2(c2d, s3d);
            p23[6] = s2d; p23[7] = mul2(s2d, c3d); p23[8] = mul2(s2d, s3d);
        }
        float c0, s0, c1, s1;
        __sincosf(xv.x, &s0, &c0);
        __sincosf(xv.y, &s1, &c1);
        const float f0a[3] = {1.0f, c0, s0};
        const float f1a[3] = {1.0f, c1, s1};

        // prefetch next chunk into the (now dead) xv registers
        const int nidx = idx + STRIDE;
        if (nidx < B) xv = x[nidx];

        // contraction: z = sum_u p01[u] * (sum_v C[u][v] * p23[v])
        ull zlo, zhi;
        {   // u = 0: p01 factor is 1 -> z initialized by inner sum directly
            ull alo = 0ull, ahi = 0ull;
#pragma unroll
            for (int v = 0; v < 9; ++v) {
                const ulonglong2 c = C2[v];
                alo = fma2(c.x, p23[v], alo);
                ahi = fma2(c.y, p23[v], ahi);
            }
            zlo = alo; zhi = ahi;
        }
#pragma unroll
        for (int u = 1; u < 9; ++u) {
            ull alo = 0ull, ahi = 0ull;
#pragma unroll
            for (int v = 0; v < 9; ++v) {
                const ulonglong2 c = C2[u * 9 + v];   // LDS.128 warp-uniform
                alo = fma2(c.x, p23[v], alo);
                ahi = fma2(c.y, p23[v], ahi);
            }
            const float puf = f0a[u / 3] * f1a[u % 3];  // static idx, 1.0 folds
            const ull pu = pk2(puf, puf);
            zlo = fma2(alo, pu, zlo);
            zhi = fma2(ahi, pu, zhi);
        }

        float z0, z1, z2, z3;
        upk2(zlo, z0, z1); upk2(zhi, z2, z3);
        out[idx] = make_float4(z0, z1, z2, z3);

        idx = nidx;
    }
}

// ---------------------------------------------------------------------------
extern "C" void kernel_launch(void* const* d_in, const int* in_sizes, int n_in,
                              void* d_out, int out_size) {
    int bx = 0, bw = 1;
    if (n_in >= 2 && in_sizes[0] == 60) { bx = 1; bw = 0; }
    const float* x   = (const float*)d_in[bx];
    const float* wts = (const float*)d_in[bw];
    const int B = in_sizes[bx] / 4;

    build_coeff_kernel<<<1, 256>>>(wts);

    cudaLaunchConfig_t cfg = {};
    cfg.gridDim  = dim3(NBLK, 1, 1);
    cfg.blockDim = dim3(TPB, 1, 1);
    cudaLaunchAttribute attrs[1];
    attrs[0].id = cudaLaunchAttributeProgrammaticStreamSerialization;
    attrs[0].val.programmaticStreamSerializationAllowed = 1;
    cfg.attrs = attrs;
    cfg.numAttrs = 1;
    cudaLaunchKernelEx(&cfg, qforward_kernel, (const float4*)x, (float4*)d_out, B);
}

// round 12
// speedup vs baseline: 1.7165x; 1.7165x over previous
#include <cuda_runtime.h>

// QuantumLayer, 2-kernel split + PDL overlap. Recombination of measured bests:
//  - eval: R2's EPT=2 TPB=256 body (66 regs, no min-blocks cap, spill-free,
//    8.42us) with features computed BEFORE the grid dependency sync so they
//    overlap the builder (R10's proven PDL structure, overhead ~3.6us -> less).
//  - builder: shuffle-parallel C construction, 1 block, unchanged since R3.
//  z_w(x) = sum_{u,v} C[w][u][v]*p01[u]*p23[v], features (1, cos x, sin x).

#define TPB 256
#define EPT 2

typedef unsigned long long ull;

__device__ float4 g_C[81];   // [u*9+v] -> (C_w0, C_w1, C_w2, C_w3)

__device__ __forceinline__ ull pk2(float lo, float hi) {
    ull r; asm("mov.b64 %0,{%1,%2};" : "=l"(r) : "f"(lo), "f"(hi)); return r;
}
__device__ __forceinline__ void upk2(ull a, float& lo, float& hi) {
    asm("mov.b64 {%0,%1},%2;" : "=f"(lo), "=f"(hi) : "l"(a));
}
__device__ __forceinline__ ull fma2(ull a, ull b, ull c) {
    ull d; asm("fma.rn.f32x2 %0,%1,%2,%3;" : "=l"(d) : "l"(a), "l"(b), "l"(c)); return d;
}
__device__ __forceinline__ ull mul2(ull a, ull b) {
    ull d; asm("mul.rn.f32x2 %0,%1,%2;" : "=l"(d) : "l"(a), "l"(b)); return d;
}

// ---------------------------------------------------------------------------
// Kernel 1: shuffle-parallel build of C. Thread tid = j*16 + i owns U[i][j].
// ---------------------------------------------------------------------------
__global__ void build_coeff_kernel(const float* __restrict__ weights) {
    cudaTriggerProgrammaticLaunchCompletion();   // let eval's prologue start now
    __shared__ float sUr[16][16], sUi[16][16];
    __shared__ float sM[256 * 4];                // [(j*16+k)*4 + w]
    const int tid = threadIdx.x;
    const int i = tid & 15;

    float vr = (i == (tid >> 4)) ? 1.0f : 0.0f;
    float vi = 0.0f;
#pragma unroll
    for (int l = 0; l < 5; ++l) {
#pragma unroll
        for (int w = 0; w < 4; ++w) {
            const float phi   = __ldg(&weights[(l * 4 + w) * 3 + 0]);
            const float theta = __ldg(&weights[(l * 4 + w) * 3 + 1]);
            const float omega = __ldg(&weights[(l * 4 + w) * 3 + 2]);
            float sp, cp, sm, cm, st, ct;
            __sincosf(0.5f * (phi + omega), &sp, &cp);
            __sincosf(0.5f * (phi - omega), &sm, &cm);
            __sincosf(0.5f * theta, &st, &ct);
            const int m = 8 >> w;
            const float pr = __shfl_xor_sync(0xffffffffu, vr, m);
            const float pi = __shfl_xor_sync(0xffffffffu, vi, m);
            const bool bit = (i & m) != 0;
            const float cAr = cp * ct;
            const float cAi = bit ? sp * ct : -sp * ct;
            const float cBr = bit ? cm * st : -cm * st;
            const float cBi = -sm * st;
            const float nvr = cAr * vr - cAi * vi + cBr * pr - cBi * pi;
            const float nvi = cAr * vi + cAi * vr + cBr * pi + cBi * pr;
            vr = nvr; vi = nvi;
        }
        const int r = (l % 3) + 1;
#pragma unroll
        for (int w = 0; w < 4; ++w) {
            const int mc = 8 >> w;
            const int mt = 8 >> ((w + r) & 3);
            const float pr = __shfl_xor_sync(0xffffffffu, vr, mt);
            const float pi = __shfl_xor_sync(0xffffffffu, vi, mt);
            if (i & mc) { vr = pr; vi = pi; }
        }
    }
    sUr[i][tid >> 4] = vr;
    sUi[i][tid >> 4] = vi;
    __syncthreads();

    {   // M_w[j][k] = sum_i sign_w(i) Re(conj U_ij * U_ik)
        const int j = tid >> 4, k = tid & 15;
        float m0 = 0.f, m1 = 0.f, m2 = 0.f, m3 = 0.f;
#pragma unroll
        for (int ii = 0; ii < 16; ++ii) {
            const float p = sUr[ii][j] * sUr[ii][k] + sUi[ii][j] * sUi[ii][k];
            m0 += (ii & 8) ? -p : p;
            m1 += (ii & 4) ? -p : p;
            m2 += (ii & 2) ? -p : p;
            m3 += (ii & 1) ? -p : p;
        }
        sM[tid * 4 + 0] = m0; sM[tid * 4 + 1] = m1;
        sM[tid * 4 + 2] = m2; sM[tid * 4 + 3] = m3;
    }
    __syncthreads();

    if (tid < 81) {  // project M_w onto (1, cos, sin)^{x4} basis
        const int t0 = tid / 27, t1 = (tid / 9) % 3, t2 = (tid / 3) % 3, t3 = tid % 3;
        const int tt[4] = {t0, t1, t2, t3};
        float a0 = 0.f, a1 = 0.f, a2 = 0.f, a3 = 0.f;
#pragma unroll
        for (int b = 0; b < 16; ++b) {
            int j = 0, k = 0; float sgn = 1.0f;
#pragma unroll
            for (int q = 0; q < 4; ++q) {
                const int o = (b >> q) & 1;
                const int ti = tt[q];
                int jq, kq;
                if (ti == 2) { jq = o; kq = 1 - o; }
                else { jq = o; kq = o; if (ti == 1 && o) sgn = -sgn; }
                j = (j << 1) | jq;
                k = (k << 1) | kq;
            }
            const float* m = &sM[(j * 16 + k) * 4];
            a0 += sgn * m[0]; a1 += sgn * m[1];
            a2 += sgn * m[2]; a3 += sgn * m[3];
        }
        const int u = t0 * 3 + t1, v = t2 * 3 + t3;
        g_C[u * 9 + v] = make_float4(a0 * 0.0625f, a1 * 0.0625f,
                                     a2 * 0.0625f, a3 * 0.0625f);
    }
}

// ---------------------------------------------------------------------------
// Kernel 2 (PDL secondary): features in prologue (overlap builder), then sync,
// stage C, packed f32x2 contraction. Exact R2 body otherwise (66 regs, 8.42us).
// ---------------------------------------------------------------------------
__global__ __launch_bounds__(TPB)
void qforward_kernel(const float4* __restrict__ x, float4* __restrict__ out, int B) {
    __shared__ __align__(16) ull shC[162];       // [uv][{w01, w23}]

    const int base = blockIdx.x * (TPB * EPT) + threadIdx.x;

    // ---------- prologue: independent of C, overlaps the builder ----------
    ull p01[EPT][9], p23[EPT][9];
    bool valid[EPT];
    const ull ONE = pk2(1.0f, 1.0f);
#pragma unroll
    for (int e = 0; e < EPT; ++e) {
        const int idx = base + e * TPB;
        valid[e] = (idx < B);
        const float4 xv = valid[e] ? x[idx] : make_float4(0.f, 0.f, 0.f, 0.f);
        float c0, s0, c1, s1, c2, s2, c3, s3;
        __sincosf(xv.x, &s0, &c0);
        __sincosf(xv.y, &s1, &c1);
        __sincosf(xv.z, &s2, &c2);
        __sincosf(xv.w, &s3, &c3);
        const ull c0d = pk2(c0, c0), s0d = pk2(s0, s0);
        const ull c1d = pk2(c1, c1), s1d = pk2(s1, s1);
        const ull c2d = pk2(c2, c2), s2d = pk2(s2, s2);
        const ull c3d = pk2(c3, c3), s3d = pk2(s3, s3);
        p01[e][0] = ONE; p01[e][1] = c1d; p01[e][2] = s1d;
        p01[e][3] = c0d; p01[e][4] = mul2(c0d, c1d); p01[e][5] = mul2(c0d, s1d);
        p01[e][6] = s0d; p01[e][7] = mul2(s0d, c1d); p01[e][8] = mul2(s0d, s1d);
        p23[e][0] = ONE; p23[e][1] = c3d; p23[e][2] = s3d;
        p23[e][3] = c2d; p23[e][4] = mul2(c2d, c3d); p23[e][5] = mul2(c2d, s3d);
        p23[e][6] = s2d; p23[e][7] = mul2(s2d, c3d); p23[e][8] = mul2(s2d, s3d);
    }

    // ---------- wait for builder's g_C, stage to shared ----------
    cudaGridDependencySynchronize();
    if (threadIdx.x < 81) {
        const float4 c = g_C[threadIdx.x];
        shC[2 * threadIdx.x]     = pk2(c.x, c.y);
        shC[2 * threadIdx.x + 1] = pk2(c.z, c.w);
    }
    __syncthreads();

    // ---------- contraction ----------
    ull zlo[EPT], zhi[EPT];
#pragma unroll
    for (int e = 0; e < EPT; ++e) { zlo[e] = 0ull; zhi[e] = 0ull; }

    const ulonglong2* __restrict__ C2 = reinterpret_cast<const ulonglong2*>(shC);
#pragma unroll
    for (int u = 0; u < 9; ++u) {
        ull alo[EPT], ahi[EPT];
#pragma unroll
        for (int e = 0; e < EPT; ++e) { alo[e] = 0ull; ahi[e] = 0ull; }
#pragma unroll
        for (int v = 0; v < 9; ++v) {
            const ulonglong2 c = C2[u * 9 + v];   // LDS.128, warp-uniform bcast
#pragma unroll
            for (int e = 0; e < EPT; ++e) {
                alo[e] = fma2(c.x, p23[e][v], alo[e]);
                ahi[e] = fma2(c.y, p23[e][v], ahi[e]);
            }
        }
#pragma unroll
        for (int e = 0; e < EPT; ++e) {
            zlo[e] = fma2(alo[e], p01[e][u], zlo[e]);
            zhi[e] = fma2(ahi[e], p01[e][u], zhi[e]);
        }
    }

#pragma unroll
    for (int e = 0; e < EPT; ++e) {
        const int idx = base + e * TPB;
        if (valid[e]) {
            float z0, z1, z2, z3;
            upk2(zlo[e], z0, z1);
            upk2(zhi[e], z2, z3);
            out[idx] = make_float4(z0, z1, z2, z3);
        }
    }
}

// ---------------------------------------------------------------------------
extern "C" void kernel_launch(void* const* d_in, const int* in_sizes, int n_in,
                              void* d_out, int out_size) {
    int bx = 0, bw = 1;
    if (n_in >= 2 && in_sizes[0] == 60) { bx = 1; bw = 0; }
    const float* x   = (const float*)d_in[bx];
    const float* wts = (const float*)d_in[bw];
    const int B = in_sizes[bx] / 4;

    build_coeff_kernel<<<1, 256>>>(wts);

    const int grid = (B + TPB * EPT - 1) / (TPB * EPT);
    cudaLaunchConfig_t cfg = {};
    cfg.gridDim  = dim3((unsigned)grid, 1, 1);
    cfg.blockDim = dim3(TPB, 1, 1);
    cudaLaunchAttribute attrs[1];
    attrs[0].id = cudaLaunchAttributeProgrammaticStreamSerialization;
    attrs[0].val.programmaticStreamSerializationAllowed = 1;
    cfg.attrs = attrs;
    cfg.numAttrs = 1;
    cudaLaunchKernelEx(&cfg, qforward_kernel, (const float4*)x, (float4*)d_out, B);
}

// round 13
// speedup vs baseline: 1.8988x; 1.1062x over previous
#include <cuda_runtime.h>

// QuantumLayer, 2-kernel split + PDL overlap (R10 shape) + register diet:
//  z_w(x) = sum_{u,v} C[w][u][v]*p01[u]*p23[v], features (1, cos x, sin x).
// Kernel 1 (1 block): shuffle-parallel C builder -> g_C.
// Kernel 2 (PDL secondary, TPB=128, EPT=2, grid=1024 -> 7 blocks/SM fully
// resident): feature prologue overlaps the builder; p23 packed, p01 kept as
// 8 scalars folded at use -> true demand ~70 regs under the 73-reg cap.

#define TPB 128
#define EPT 2

typedef unsigned long long ull;

__device__ float4 g_C[81];   // [u*9+v] -> (C_w0, C_w1, C_w2, C_w3)

__device__ __forceinline__ ull pk2(float lo, float hi) {
    ull r; asm("mov.b64 %0,{%1,%2};" : "=l"(r) : "f"(lo), "f"(hi)); return r;
}
__device__ __forceinline__ void upk2(ull a, float& lo, float& hi) {
    asm("mov.b64 {%0,%1},%2;" : "=f"(lo), "=f"(hi) : "l"(a));
}
__device__ __forceinline__ ull fma2(ull a, ull b, ull c) {
    ull d; asm("fma.rn.f32x2 %0,%1,%2,%3;" : "=l"(d) : "l"(a), "l"(b), "l"(c)); return d;
}
__device__ __forceinline__ ull mul2(ull a, ull b) {
    ull d; asm("mul.rn.f32x2 %0,%1,%2;" : "=l"(d) : "l"(a), "l"(b)); return d;
}

// ---------------------------------------------------------------------------
// Kernel 1: shuffle-parallel build of C. Thread tid = j*16 + i owns U[i][j].
// ---------------------------------------------------------------------------
__global__ void build_coeff_kernel(const float* __restrict__ weights) {
    cudaTriggerProgrammaticLaunchCompletion();   // let eval's prologue start now
    __shared__ float sUr[16][16], sUi[16][16];
    __shared__ float sM[256 * 4];                // [(j*16+k)*4 + w]
    const int tid = threadIdx.x;
    const int i = tid & 15;

    float vr = (i == (tid >> 4)) ? 1.0f : 0.0f;
    float vi = 0.0f;
#pragma unroll
    for (int l = 0; l < 5; ++l) {
#pragma unroll
        for (int w = 0; w < 4; ++w) {
            const float phi   = __ldg(&weights[(l * 4 + w) * 3 + 0]);
            const float theta = __ldg(&weights[(l * 4 + w) * 3 + 1]);
            const float omega = __ldg(&weights[(l * 4 + w) * 3 + 2]);
            float sp, cp, sm, cm, st, ct;
            __sincosf(0.5f * (phi + omega), &sp, &cp);
            __sincosf(0.5f * (phi - omega), &sm, &cm);
            __sincosf(0.5f * theta, &st, &ct);
            const int m = 8 >> w;
            const float pr = __shfl_xor_sync(0xffffffffu, vr, m);
            const float pi = __shfl_xor_sync(0xffffffffu, vi, m);
            const bool bit = (i & m) != 0;
            const float cAr = cp * ct;
            const float cAi = bit ? sp * ct : -sp * ct;
            const float cBr = bit ? cm * st : -cm * st;
            const float cBi = -sm * st;
            const float nvr = cAr * vr - cAi * vi + cBr * pr - cBi * pi;
            const float nvi = cAr * vi + cAi * vr + cBr * pi + cBi * pr;
            vr = nvr; vi = nvi;
        }
        const int r = (l % 3) + 1;
#pragma unroll
        for (int w = 0; w < 4; ++w) {
            const int mc = 8 >> w;
            const int mt = 8 >> ((w + r) & 3);
            const float pr = __shfl_xor_sync(0xffffffffu, vr, mt);
            const float pi = __shfl_xor_sync(0xffffffffu, vi, mt);
            if (i & mc) { vr = pr; vi = pi; }
        }
    }
    sUr[i][tid >> 4] = vr;
    sUi[i][tid >> 4] = vi;
    __syncthreads();

    {   // M_w[j][k] = sum_i sign_w(i) Re(conj U_ij * U_ik)
        const int j = tid >> 4, k = tid & 15;
        float m0 = 0.f, m1 = 0.f, m2 = 0.f, m3 = 0.f;
#pragma unroll
        for (int ii = 0; ii < 16; ++ii) {
            const float p = sUr[ii][j] * sUr[ii][k] + sUi[ii][j] * sUi[ii][k];
            m0 += (ii & 8) ? -p : p;
            m1 += (ii & 4) ? -p : p;
            m2 += (ii & 2) ? -p : p;
            m3 += (ii & 1) ? -p : p;
        }
        sM[tid * 4 + 0] = m0; sM[tid * 4 + 1] = m1;
        sM[tid * 4 + 2] = m2; sM[tid * 4 + 3] = m3;
    }
    __syncthreads();

    if (tid < 81) {  // project M_w onto (1, cos, sin)^{x4} basis
        const int t0 = tid / 27, t1 = (tid / 9) % 3, t2 = (tid / 3) % 3, t3 = tid % 3;
        const int tt[4] = {t0, t1, t2, t3};
        float a0 = 0.f, a1 = 0.f, a2 = 0.f, a3 = 0.f;
#pragma unroll
        for (int b = 0; b < 16; ++b) {
            int j = 0, k = 0; float sgn = 1.0f;
#pragma unroll
            for (int q = 0; q < 4; ++q) {
                const int o = (b >> q) & 1;
                const int ti = tt[q];
                int jq, kq;
                if (ti == 2) { jq = o; kq = 1 - o; }
                else { jq = o; kq = o; if (ti == 1 && o) sgn = -sgn; }
                j = (j << 1) | jq;
                k = (k << 1) | kq;
            }
            const float* m = &sM[(j * 16 + k) * 4];
            a0 += sgn * m[0]; a1 += sgn * m[1];
            a2 += sgn * m[2]; a3 += sgn * m[3];
        }
        const int u = t0 * 3 + t1, v = t2 * 3 + t3;
        g_C[u * 9 + v] = make_float4(a0 * 0.0625f, a1 * 0.0625f,
                                     a2 * 0.0625f, a3 * 0.0625f);
    }
}

// ---------------------------------------------------------------------------
// Kernel 2 (PDL secondary): straight-line EPT=2, p01 as scalars, slim regs.
// ---------------------------------------------------------------------------
__global__ __launch_bounds__(TPB, 7)
void qforward_kernel(const float4* __restrict__ x, float4* __restrict__ out, int B) {
    __shared__ __align__(16) ull shC[162];       // [uv][{w01, w23}]

    const int base = blockIdx.x * (TPB * EPT) + threadIdx.x;

    // ---------- prologue: independent of C, overlaps the builder ----------
    ull p23[EPT][9];
    float f0[EPT][3], f1[EPT][3];                // {1, cos, sin} factors, q0/q1
    bool valid[EPT];
    const ull ONE = pk2(1.0f, 1.0f);
#pragma unroll
    for (int e = 0; e < EPT; ++e) {
        const int idx = base + e * TPB;
        valid[e] = (idx < B);
        const float4 xv = valid[e] ? x[idx] : make_float4(0.f, 0.f, 0.f, 0.f);
        float c2, s2, c3, s3;
        __sincosf(xv.z, &s2, &c2);
        __sincosf(xv.w, &s3, &c3);
        const ull c2d = pk2(c2, c2), s2d = pk2(s2, s2);
        const ull c3d = pk2(c3, c3), s3d = pk2(s3, s3);
        p23[e][0] = ONE; p23[e][1] = c3d; p23[e][2] = s3d;
        p23[e][3] = c2d; p23[e][4] = mul2(c2d, c3d); p23[e][5] = mul2(c2d, s3d);
        p23[e][6] = s2d; p23[e][7] = mul2(s2d, c3d); p23[e][8] = mul2(s2d, s3d);
        float c0, s0, c1, s1;
        __sincosf(xv.x, &s0, &c0);
        __sincosf(xv.y, &s1, &c1);
        f0[e][0] = 1.0f; f0[e][1] = c0; f0[e][2] = s0;
        f1[e][0] = 1.0f; f1[e][1] = c1; f1[e][2] = s1;
    }

    // ---------- wait for builder's g_C, stage to shared ----------
    cudaGridDependencySynchronize();
    if (threadIdx.x < 81) {
        const float4 c = g_C[threadIdx.x];
        shC[2 * threadIdx.x]     = pk2(c.x, c.y);
        shC[2 * threadIdx.x + 1] = pk2(c.z, c.w);
    }
    __syncthreads();

    // ---------- contraction ----------
    const ulonglong2* __restrict__ C2 = reinterpret_cast<const ulonglong2*>(shC);
    ull zlo[EPT], zhi[EPT];

    {   // u = 0: p01 factor is 1 -> z initialized by inner sums directly
        ull alo[EPT] = {0ull, 0ull}, ahi[EPT] = {0ull, 0ull};
#pragma unroll
        for (int v = 0; v < 9; ++v) {
            const ulonglong2 c = C2[v];
#pragma unroll
            for (int e = 0; e < EPT; ++e) {
                alo[e] = fma2(c.x, p23[e][v], alo[e]);
                ahi[e] = fma2(c.y, p23[e][v], ahi[e]);
            }
        }
#pragma unroll
        for (int e = 0; e < EPT; ++e) { zlo[e] = alo[e]; zhi[e] = ahi[e]; }
    }
#pragma unroll
    for (int u = 1; u < 9; ++u) {
        ull alo[EPT] = {0ull, 0ull}, ahi[EPT] = {0ull, 0ull};
#pragma unroll
        for (int v = 0; v < 9; ++v) {
            const ulonglong2 c = C2[u * 9 + v];   // LDS.128, warp-uniform bcast
#pragma unroll
            for (int e = 0; e < EPT; ++e) {
                alo[e] = fma2(c.x, p23[e][v], alo[e]);
                ahi[e] = fma2(c.y, p23[e][v], ahi[e]);
            }
        }
#pragma unroll
        for (int e = 0; e < EPT; ++e) {
            const float puf = f0[e][u / 3] * f1[e][u % 3];  // static idx; 1.0 folds
            const ull pu = pk2(puf, puf);
            zlo[e] = fma2(alo[e], pu, zlo[e]);
            zhi[e] = fma2(ahi[e], pu, zhi[e]);
        }
    }

#pragma unroll
    for (int e = 0; e < EPT; ++e) {
        const int idx = base + e * TPB;
        if (valid[e]) {
            float z0, z1, z2, z3;
            upk2(zlo[e], z0, z1);
            upk2(zhi[e], z2, z3);
            out[idx] = make_float4(z0, z1, z2, z3);
        }
    }
}

// ---------------------------------------------------------------------------
extern "C" void kernel_launch(void* const* d_in, const int* in_sizes, int n_in,
                              void* d_out, int out_size) {
    int bx = 0, bw = 1;
    if (n_in >= 2 && in_sizes[0] == 60) { bx = 1; bw = 0; }
    const float* x   = (const float*)d_in[bx];
    const float* wts = (const float*)d_in[bw];
    const int B = in_sizes[bx] / 4;

    build_coeff_kernel<<<1, 256>>>(wts);

    const int grid = (B + TPB * EPT - 1) / (TPB * EPT);
    cudaLaunchConfig_t cfg = {};
    cfg.gridDim  = dim3((unsigned)grid, 1, 1);
    cfg.blockDim = dim3(TPB, 1, 1);
    cudaLaunchAttribute attrs[1];
    attrs[0].id = cudaLaunchAttributeProgrammaticStreamSerialization;
    attrs[0].val.programmaticStreamSerializationAllowed = 1;
    cfg.attrs = attrs;
    cfg.numAttrs = 1;
    cudaLaunchKernelEx(&cfg, qforward_kernel, (const float4*)x, (float4*)d_out, B);
}